// round 12
// baseline (speedup 1.0000x reference)
#include <cuda_runtime.h>
#include <cuda_fp16.h>
#include <cuda_bf16.h>
#include <cstdint>

#define N_NODES  50000
#define N_EDGES  800000
#define HIDDEN   128
#define N_GRAPHS 512

#define SCAN_BS  512
#define SCAN_NB  ((N_NODES + SCAN_BS - 1) / SCAN_BS)   // 98

// ---------------------------------------------------------------------------
// Static device scratch (~33 MB). Referenced ONLY from device code.
// Zero-invariants restored in-call: g_pool/g_cnt zeroed by deg_kernel blk 0
// (before scan_k1 uses them); g_deg zeroed by last reader scan_k3; g_done
// reset by the last agg<2> block.
// ---------------------------------------------------------------------------
__device__ int    g_deg[N_NODES];
__device__ int    g_ptr[N_NODES];
__device__ int    g_rank[N_EDGES];     // per-edge within-dst rank (from deg pass)
__device__ int    g_csr[N_EDGES];
__device__ int    g_bsum[SCAN_NB];
__device__ float  g_dinv[N_NODES];
__device__ __half g_ph[(size_t)N_NODES * HIDDEN];  // fp16 pre-scaled features
__device__ __half g_hh[(size_t)N_NODES * HIDDEN];  // fp16 relu'd layer-1 output
__device__ float  g_pool[N_GRAPHS];
__device__ float  g_cnt[N_GRAPHS];
__device__ unsigned g_done;

__device__ __forceinline__ float ldcg_f(const float* p) {
    float v;
    asm volatile("ld.global.cg.f32 %0, [%1];" : "=f"(v) : "l"(p));
    return v;
}

// ---------------------------------------------------------------------------
// Degree histogram; atomic return value IS the edge's rank. Block 0 restores
// pool/cnt zeros for this call.
// ---------------------------------------------------------------------------
__global__ void __launch_bounds__(256) deg_kernel(const int* __restrict__ dst) {
    if (blockIdx.x == 0) {
        for (int i = threadIdx.x; i < N_GRAPHS; i += 256) {
            g_pool[i] = 0.0f;
            g_cnt[i]  = 0.0f;
        }
    }
    int e = blockIdx.x * blockDim.x + threadIdx.x;
    if (e < N_EDGES) g_rank[e] = atomicAdd(&g_deg[dst[e]], 1);
}

// scan stage 1 + dinv + graph counts fused
__global__ void __launch_bounds__(SCAN_BS) scan_k1(const int* __restrict__ batch) {
    __shared__ int s[SCAN_BS];
    int i = blockIdx.x * SCAN_BS + threadIdx.x;
    int d = (i < N_NODES) ? g_deg[i] : 0;
    if (i < N_NODES) {
        g_dinv[i] = rsqrtf((float)d + 1.0f);
        atomicAdd(&g_cnt[batch[i]], 1.0f);
    }
    s[threadIdx.x] = d;
    __syncthreads();
    for (int off = SCAN_BS / 2; off > 0; off >>= 1) {
        if (threadIdx.x < off) s[threadIdx.x] += s[threadIdx.x + off];
        __syncthreads();
    }
    if (threadIdx.x == 0) g_bsum[blockIdx.x] = s[0];
}

// Block-local exclusive scan; warp 0 reduces g_bsum[0..b-1] for the block
// offset. Zeroes g_deg (last reader) to restore the cross-call invariant.
__global__ void __launch_bounds__(SCAN_BS) scan_k3() {
    __shared__ int s[SCAN_BS];
    __shared__ int sprefix;
    const int b = blockIdx.x;
    int i = b * SCAN_BS + threadIdx.x;
    int d = (i < N_NODES) ? g_deg[i] : 0;
    if (i < N_NODES) g_deg[i] = 0;                 // self-restore
    s[threadIdx.x] = d;
    __syncthreads();

    if (threadIdx.x < 32) {
        int acc = 0;
        for (int j = threadIdx.x; j < b; j += 32) acc += g_bsum[j];
        #pragma unroll
        for (int off = 16; off; off >>= 1)
            acc += __shfl_xor_sync(0xffffffffu, acc, off);
        if (threadIdx.x == 0) sprefix = acc;
    }

    for (int off = 1; off < SCAN_BS; off <<= 1) {
        int v = (threadIdx.x >= off) ? s[threadIdx.x - off] : 0;
        __syncthreads();
        s[threadIdx.x] += v;
        __syncthreads();
    }
    if (i < N_NODES) g_ptr[i] = sprefix + s[threadIdx.x] - d;   // exclusive
}

// CSR fill with NO atomics: pos = ptr[dst] + rank[e].
__global__ void __launch_bounds__(256) fill_kernel(const int* __restrict__ src,
                                                   const int* __restrict__ dst) {
    int e = blockIdx.x * blockDim.x + threadIdx.x;
    if (e < N_EDGES) {
        int d = dst[e];
        g_csr[g_ptr[d] + g_rank[e]] = src[e];
    }
}

// ---------------------------------------------------------------------------
// Tensor-core GEMM: g_ph[row] = half( (in[row] @ W) * dinv[row] )
//   MODE 0: in = X fp32 (arg)     MODE 1: in = g_hh fp16 (device global)
// ---------------------------------------------------------------------------
#define AS_STRIDE 136
#define GEMM_TC_SMEM (2 * 128 * AS_STRIDE * 2)   // 69632 B

__device__ __forceinline__ uint32_t smem_u32(const void* p) {
    return (uint32_t)__cvta_generic_to_shared(p);
}
__device__ __forceinline__ void ldsm_x4(uint32_t& r0, uint32_t& r1,
                                        uint32_t& r2, uint32_t& r3, uint32_t a) {
    asm volatile("ldmatrix.sync.aligned.m8n8.x4.shared.b16 {%0,%1,%2,%3},[%4];"
                 : "=r"(r0), "=r"(r1), "=r"(r2), "=r"(r3) : "r"(a));
}
__device__ __forceinline__ void ldsm_x2t(uint32_t& r0, uint32_t& r1, uint32_t a) {
    asm volatile("ldmatrix.sync.aligned.m8n8.x2.trans.shared.b16 {%0,%1},[%2];"
                 : "=r"(r0), "=r"(r1) : "r"(a));
}
__device__ __forceinline__ void mma16816(float* c, const uint32_t* a, const uint32_t* b) {
    asm volatile("mma.sync.aligned.m16n8k16.row.col.f32.f16.f16.f32 "
                 "{%0,%1,%2,%3},{%4,%5,%6,%7},{%8,%9},{%0,%1,%2,%3};"
                 : "+f"(c[0]), "+f"(c[1]), "+f"(c[2]), "+f"(c[3])
                 : "r"(a[0]), "r"(a[1]), "r"(a[2]), "r"(a[3]), "r"(b[0]), "r"(b[1]));
}

template <int MODE>
__global__ void __launch_bounds__(256) gemm_tc(const float* __restrict__ X,
                                               const float* __restrict__ W) {
    extern __shared__ __half smem[];
    __half* As = smem;                         // 128 x 136
    __half* Ws = smem + 128 * AS_STRIDE;       // 128 x 136 (row = k, col = n)

    const int tid = threadIdx.x;
    const int row0 = blockIdx.x * 128;

    const float4* W4 = reinterpret_cast<const float4*>(W);
    for (int j = tid; j < 4096; j += 256) {
        int r = j >> 5, s = j & 31;
        float4 v = W4[j];
        __half2 h0 = __floats2half2_rn(v.x, v.y);
        __half2 h1 = __floats2half2_rn(v.z, v.w);
        uint2 pk;
        pk.x = *reinterpret_cast<uint32_t*>(&h0);
        pk.y = *reinterpret_cast<uint32_t*>(&h1);
        *reinterpret_cast<uint2*>(Ws + r * AS_STRIDE + s * 4) = pk;
    }
    if (MODE == 0) {
        for (int j = tid; j < 4096; j += 256) {     // 128 rows x 32 segs
            int r = j >> 5, s = j & 31;
            int row = row0 + r;
            float4 v = make_float4(0.f, 0.f, 0.f, 0.f);
            if (row < N_NODES)
                v = reinterpret_cast<const float4*>(X + (size_t)row * HIDDEN)[s];
            __half2 h0 = __floats2half2_rn(v.x, v.y);
            __half2 h1 = __floats2half2_rn(v.z, v.w);
            uint2 pk;
            pk.x = *reinterpret_cast<uint32_t*>(&h0);
            pk.y = *reinterpret_cast<uint32_t*>(&h1);
            *reinterpret_cast<uint2*>(As + r * AS_STRIDE + s * 4) = pk;
        }
    } else {
        for (int j = tid; j < 2048; j += 256) {     // 128 rows x 16 uint4 segs
            int r = j >> 4, s = j & 15;
            int row = row0 + r;
            uint4 v = make_uint4(0u, 0u, 0u, 0u);
            if (row < N_NODES)
                v = reinterpret_cast<const uint4*>(g_hh)[(size_t)row * 16 + s];
            *reinterpret_cast<uint4*>(As + r * AS_STRIDE + s * 8) = v;
        }
    }
    __syncthreads();

    const int w = tid >> 5, lane = tid & 31;
    const int m0 = (w >> 1) * 32;
    const int n0g = (w & 1) * 64;

    float c[2][8][4];
    #pragma unroll
    for (int mt = 0; mt < 2; mt++)
        #pragma unroll
        for (int nt = 0; nt < 8; nt++)
            #pragma unroll
            for (int q = 0; q < 4; q++) c[mt][nt][q] = 0.f;

    const int arow = lane & 15, acol = (lane >> 4) * 8;
    const int brow = lane & 15;

    #pragma unroll
    for (int kc = 0; kc < 8; kc++) {
        const int k0 = kc * 16;
        uint32_t a[2][4];
        #pragma unroll
        for (int mt = 0; mt < 2; mt++) {
            uint32_t addr = smem_u32(As + (m0 + mt * 16 + arow) * AS_STRIDE + k0 + acol);
            ldsm_x4(a[mt][0], a[mt][1], a[mt][2], a[mt][3], addr);
        }
        #pragma unroll
        for (int nt = 0; nt < 8; nt++) {
            uint32_t b[2];
            uint32_t baddr = smem_u32(Ws + (k0 + brow) * AS_STRIDE + n0g + nt * 8);
            ldsm_x2t(b[0], b[1], baddr);
            mma16816(c[0][nt], a[0], b);
            mma16816(c[1][nt], a[1], b);
        }
    }

    #pragma unroll
    for (int mt = 0; mt < 2; mt++) {
        int r0g = row0 + m0 + mt * 16 + (lane >> 2);
        int r1g = r0g + 8;
        float d0 = (r0g < N_NODES) ? g_dinv[r0g] : 0.f;
        float d1 = (r1g < N_NODES) ? g_dinv[r1g] : 0.f;
        #pragma unroll
        for (int nt = 0; nt < 8; nt++) {
            int col = n0g + nt * 8 + 2 * (lane & 3);
            if (r0g < N_NODES) {
                __half2 h = __floats2half2_rn(c[mt][nt][0] * d0, c[mt][nt][1] * d0);
                *reinterpret_cast<__half2*>(g_ph + (size_t)r0g * HIDDEN + col) = h;
            }
            if (r1g < N_NODES) {
                __half2 h = __floats2half2_rn(c[mt][nt][2] * d1, c[mt][nt][3] * d1);
                *reinterpret_cast<__half2*>(g_ph + (size_t)r1g * HIDDEN + col) = h;
            }
        }
    }
}

// ---------------------------------------------------------------------------
// CSR aggregation v1 (proven): one warp per node, lane l owns uint2 (8B),
// one fully-coalesced 256B row load per neighbor. deg = ptr[n+1] - ptr[n].
// LAYER 2 additionally runs the output epilogue in its last-finishing block.
// ---------------------------------------------------------------------------
__device__ __forceinline__ void acc_h4(float4& acc, uint2 raw) {
    __half2 a = *reinterpret_cast<__half2*>(&raw.x);
    __half2 b = *reinterpret_cast<__half2*>(&raw.y);
    float2 f0 = __half22float2(a);
    float2 f1 = __half22float2(b);
    acc.x += f0.x; acc.y += f0.y; acc.z += f1.x; acc.w += f1.y;
}

template <int LAYER>
__global__ void __launch_bounds__(256) agg_kernel(const float* __restrict__ bias,
                                                  const float* __restrict__ Wl,
                                                  const int* __restrict__ batch,
                                                  const float* __restrict__ bl,
                                                  float* __restrict__ out) {
    int t = blockIdx.x * blockDim.x + threadIdx.x;
    int n = t >> 5;                 // grid sized so n < N_NODES always
    int l = t & 31;

    const uint2* P2 = reinterpret_cast<const uint2*>(g_ph);
    float4 acc = make_float4(0.f, 0.f, 0.f, 0.f);
    acc_h4(acc, __ldg(&P2[(size_t)n * 32 + l]));   // self term

    int base = g_ptr[n];
    int deg  = ((n + 1 < N_NODES) ? g_ptr[n + 1] : N_EDGES) - base;
    int i = 0;
    for (; i + 4 <= deg; i += 4) {
        int s0 = g_csr[base + i + 0];
        int s1 = g_csr[base + i + 1];
        int s2 = g_csr[base + i + 2];
        int s3 = g_csr[base + i + 3];
        uint2 v0 = __ldg(&P2[(size_t)s0 * 32 + l]);
        uint2 v1 = __ldg(&P2[(size_t)s1 * 32 + l]);
        uint2 v2 = __ldg(&P2[(size_t)s2 * 32 + l]);
        uint2 v3 = __ldg(&P2[(size_t)s3 * 32 + l]);
        acc_h4(acc, v0); acc_h4(acc, v1); acc_h4(acc, v2); acc_h4(acc, v3);
    }
    for (; i < deg; i++) {
        int s = g_csr[base + i];
        acc_h4(acc, __ldg(&P2[(size_t)s * 32 + l]));
    }

    float di = g_dinv[n];
    float4 b = __ldg(reinterpret_cast<const float4*>(bias) + l);
    float h0 = fmaxf(di * acc.x + b.x, 0.f);
    float h1 = fmaxf(di * acc.y + b.y, 0.f);
    float h2 = fmaxf(di * acc.z + b.z, 0.f);
    float h3 = fmaxf(di * acc.w + b.w, 0.f);

    if (LAYER == 1) {
        __half2 ha = __floats2half2_rn(h0, h1);
        __half2 hb = __floats2half2_rn(h2, h3);
        uint2 pk;
        pk.x = *reinterpret_cast<uint32_t*>(&ha);
        pk.y = *reinterpret_cast<uint32_t*>(&hb);
        reinterpret_cast<uint2*>(g_hh)[(size_t)n * 32 + l] = pk;
    } else {
        float4 wl = __ldg(reinterpret_cast<const float4*>(Wl) + l);
        float s = h0 * wl.x + h1 * wl.y + h2 * wl.z + h3 * wl.w;
        #pragma unroll
        for (int off = 16; off; off >>= 1) s += __shfl_xor_sync(0xffffffffu, s, off);
        if (l == 0) atomicAdd(&g_pool[__ldg(&batch[n])], s);

        // ---- fused output epilogue: last block to finish does the mean+bias
        __shared__ int isLast;
        __syncthreads();                       // all pool atomics in block issued
        if (threadIdx.x == 0) {
            __threadfence();
            unsigned done = atomicAdd(&g_done, 1u);
            isLast = (done == gridDim.x - 1) ? 1 : 0;
        }
        __syncthreads();
        if (isLast) {
            float blv = bl[0];
            for (int g = threadIdx.x; g < N_GRAPHS; g += 256) {
                float p = ldcg_f(&g_pool[g]);
                float c = ldcg_f(&g_cnt[g]);
                out[g] = p / fmaxf(c, 1.0f) + blv;
            }
            if (threadIdx.x == 0) g_done = 0;  // restore invariant
        }
    }
}

// ---------------------------------------------------------------------------
extern "C" void kernel_launch(void* const* d_in, const int* in_sizes, int n_in,
                              void* d_out, int out_size) {
    const float* x     = (const float*)d_in[0];
    const int*   ei    = (const int*)  d_in[1];
    const int*   batch = (const int*)  d_in[2];
    const float* W1    = (const float*)d_in[3];
    const float* b1    = (const float*)d_in[4];
    const float* W2    = (const float*)d_in[5];
    const float* b2    = (const float*)d_in[6];
    const float* Wl    = (const float*)d_in[7];
    const float* bl    = (const float*)d_in[8];
    const int* src = ei;
    const int* dst = ei + N_EDGES;

    cudaFuncSetAttribute(gemm_tc<0>, cudaFuncAttributeMaxDynamicSharedMemorySize,
                         GEMM_TC_SMEM);
    cudaFuncSetAttribute(gemm_tc<1>, cudaFuncAttributeMaxDynamicSharedMemorySize,
                         GEMM_TC_SMEM);

    const int EB  = (N_EDGES + 255) / 256;
    const int TCB = (N_NODES + 127) / 128;          // 391
    const int AGB = (N_NODES * 32) / 256;           // 6250 exactly

    // --- graph structure (4 launches, fill now atomic-free) ---
    deg_kernel<<<EB, 256>>>(dst);            // + rank capture + pool/cnt restore
    scan_k1<<<SCAN_NB, SCAN_BS>>>(batch);    // + dinv + graph counts
    scan_k3<<<SCAN_NB, SCAN_BS>>>();         // + own offset + g_deg restore
    fill_kernel<<<EB, 256>>>(src, dst);

    // --- layer 1 ---
    gemm_tc<0><<<TCB, 256, GEMM_TC_SMEM>>>(x, W1);
    agg_kernel<1><<<AGB, 256>>>(b1, nullptr, nullptr, nullptr, nullptr);

    // --- layer 2 (epilogue + Wl dot + pooling + output all fused) ---
    gemm_tc<1><<<TCB, 256, GEMM_TC_SMEM>>>(nullptr, W2);
    agg_kernel<2><<<AGB, 256>>>(b2, Wl, batch, bl, (float*)d_out);
}

// round 13
// speedup vs baseline: 1.0553x; 1.0553x over previous
#include <cuda_runtime.h>
#include <cuda_fp16.h>
#include <cuda_bf16.h>
#include <cstdint>

#define N_NODES  50000
#define N_EDGES  800000
#define HIDDEN   128
#define N_GRAPHS 512

#define SCAN_BS  512
#define SCAN_NB  ((N_NODES + SCAN_BS - 1) / SCAN_BS)   // 98

// ---------------------------------------------------------------------------
// Static device scratch (~33 MB). Referenced ONLY from device code.
// Zero-invariants restored in-call: g_pool/g_cnt zeroed by deg_kernel blk 0
// (before scan_k1 uses them); g_deg zeroed by last reader scan_k3.
// ---------------------------------------------------------------------------
__device__ int    g_deg[N_NODES];
__device__ int    g_ptr[N_NODES];
__device__ int    g_rank[N_EDGES];     // per-edge within-dst rank (from deg pass)
__device__ int    g_csr[N_EDGES];
__device__ int    g_bsum[SCAN_NB];
__device__ float  g_dinv[N_NODES];
__device__ __half g_ph[(size_t)N_NODES * HIDDEN];  // fp16 pre-scaled features
__device__ __half g_hh[(size_t)N_NODES * HIDDEN];  // fp16 relu'd layer-1 output
__device__ float  g_pool[N_GRAPHS];
__device__ float  g_cnt[N_GRAPHS];

// ---------------------------------------------------------------------------
// Degree histogram; atomic return value IS the edge's rank. Block 0 restores
// pool/cnt zeros for this call.
// ---------------------------------------------------------------------------
__global__ void __launch_bounds__(256) deg_kernel(const int* __restrict__ dst) {
    if (blockIdx.x == 0) {
        for (int i = threadIdx.x; i < N_GRAPHS; i += 256) {
            g_pool[i] = 0.0f;
            g_cnt[i]  = 0.0f;
        }
    }
    int e = blockIdx.x * blockDim.x + threadIdx.x;
    if (e < N_EDGES) g_rank[e] = atomicAdd(&g_deg[dst[e]], 1);
}

// scan stage 1 + dinv + graph counts fused
__global__ void __launch_bounds__(SCAN_BS) scan_k1(const int* __restrict__ batch) {
    __shared__ int s[SCAN_BS];
    int i = blockIdx.x * SCAN_BS + threadIdx.x;
    int d = (i < N_NODES) ? g_deg[i] : 0;
    if (i < N_NODES) {
        g_dinv[i] = rsqrtf((float)d + 1.0f);
        atomicAdd(&g_cnt[batch[i]], 1.0f);
    }
    s[threadIdx.x] = d;
    __syncthreads();
    for (int off = SCAN_BS / 2; off > 0; off >>= 1) {
        if (threadIdx.x < off) s[threadIdx.x] += s[threadIdx.x + off];
        __syncthreads();
    }
    if (threadIdx.x == 0) g_bsum[blockIdx.x] = s[0];
}

// Block-local exclusive scan; warp 0 reduces g_bsum[0..b-1] for the block
// offset. Zeroes g_deg (last reader) to restore the cross-call invariant.
__global__ void __launch_bounds__(SCAN_BS) scan_k3() {
    __shared__ int s[SCAN_BS];
    __shared__ int sprefix;
    const int b = blockIdx.x;
    int i = b * SCAN_BS + threadIdx.x;
    int d = (i < N_NODES) ? g_deg[i] : 0;
    if (i < N_NODES) g_deg[i] = 0;                 // self-restore
    s[threadIdx.x] = d;
    __syncthreads();

    if (threadIdx.x < 32) {
        int acc = 0;
        for (int j = threadIdx.x; j < b; j += 32) acc += g_bsum[j];
        #pragma unroll
        for (int off = 16; off; off >>= 1)
            acc += __shfl_xor_sync(0xffffffffu, acc, off);
        if (threadIdx.x == 0) sprefix = acc;
    }

    for (int off = 1; off < SCAN_BS; off <<= 1) {
        int v = (threadIdx.x >= off) ? s[threadIdx.x - off] : 0;
        __syncthreads();
        s[threadIdx.x] += v;
        __syncthreads();
    }
    if (i < N_NODES) g_ptr[i] = sprefix + s[threadIdx.x] - d;   // exclusive
}

// CSR fill with NO atomics: pos = ptr[dst] + rank[e].
__global__ void __launch_bounds__(256) fill_kernel(const int* __restrict__ src,
                                                   const int* __restrict__ dst) {
    int e = blockIdx.x * blockDim.x + threadIdx.x;
    if (e < N_EDGES) {
        int d = dst[e];
        g_csr[g_ptr[d] + g_rank[e]] = src[e];
    }
}

// ---------------------------------------------------------------------------
// Tensor-core GEMM: g_ph[row] = half( (in[row] @ W) * dinv[row] )
//   MODE 0: in = X fp32 (arg)     MODE 1: in = g_hh fp16 (device global)
// ---------------------------------------------------------------------------
#define AS_STRIDE 136
#define GEMM_TC_SMEM (2 * 128 * AS_STRIDE * 2)   // 69632 B

__device__ __forceinline__ uint32_t smem_u32(const void* p) {
    return (uint32_t)__cvta_generic_to_shared(p);
}
__device__ __forceinline__ void ldsm_x4(uint32_t& r0, uint32_t& r1,
                                        uint32_t& r2, uint32_t& r3, uint32_t a) {
    asm volatile("ldmatrix.sync.aligned.m8n8.x4.shared.b16 {%0,%1,%2,%3},[%4];"
                 : "=r"(r0), "=r"(r1), "=r"(r2), "=r"(r3) : "r"(a));
}
__device__ __forceinline__ void ldsm_x2t(uint32_t& r0, uint32_t& r1, uint32_t a) {
    asm volatile("ldmatrix.sync.aligned.m8n8.x2.trans.shared.b16 {%0,%1},[%2];"
                 : "=r"(r0), "=r"(r1) : "r"(a));
}
__device__ __forceinline__ void mma16816(float* c, const uint32_t* a, const uint32_t* b) {
    asm volatile("mma.sync.aligned.m16n8k16.row.col.f32.f16.f16.f32 "
                 "{%0,%1,%2,%3},{%4,%5,%6,%7},{%8,%9},{%0,%1,%2,%3};"
                 : "+f"(c[0]), "+f"(c[1]), "+f"(c[2]), "+f"(c[3])
                 : "r"(a[0]), "r"(a[1]), "r"(a[2]), "r"(a[3]), "r"(b[0]), "r"(b[1]));
}

template <int MODE>
__global__ void __launch_bounds__(256) gemm_tc(const float* __restrict__ X,
                                               const float* __restrict__ W) {
    extern __shared__ __half smem[];
    __half* As = smem;                         // 128 x 136
    __half* Ws = smem + 128 * AS_STRIDE;       // 128 x 136 (row = k, col = n)

    const int tid = threadIdx.x;
    const int row0 = blockIdx.x * 128;

    const float4* W4 = reinterpret_cast<const float4*>(W);
    for (int j = tid; j < 4096; j += 256) {
        int r = j >> 5, s = j & 31;
        float4 v = W4[j];
        __half2 h0 = __floats2half2_rn(v.x, v.y);
        __half2 h1 = __floats2half2_rn(v.z, v.w);
        uint2 pk;
        pk.x = *reinterpret_cast<uint32_t*>(&h0);
        pk.y = *reinterpret_cast<uint32_t*>(&h1);
        *reinterpret_cast<uint2*>(Ws + r * AS_STRIDE + s * 4) = pk;
    }
    if (MODE == 0) {
        for (int j = tid; j < 4096; j += 256) {     // 128 rows x 32 segs
            int r = j >> 5, s = j & 31;
            int row = row0 + r;
            float4 v = make_float4(0.f, 0.f, 0.f, 0.f);
            if (row < N_NODES)
                v = reinterpret_cast<const float4*>(X + (size_t)row * HIDDEN)[s];
            __half2 h0 = __floats2half2_rn(v.x, v.y);
            __half2 h1 = __floats2half2_rn(v.z, v.w);
            uint2 pk;
            pk.x = *reinterpret_cast<uint32_t*>(&h0);
            pk.y = *reinterpret_cast<uint32_t*>(&h1);
            *reinterpret_cast<uint2*>(As + r * AS_STRIDE + s * 4) = pk;
        }
    } else {
        for (int j = tid; j < 2048; j += 256) {     // 128 rows x 16 uint4 segs
            int r = j >> 4, s = j & 15;
            int row = row0 + r;
            uint4 v = make_uint4(0u, 0u, 0u, 0u);
            if (row < N_NODES)
                v = reinterpret_cast<const uint4*>(g_hh)[(size_t)row * 16 + s];
            *reinterpret_cast<uint4*>(As + r * AS_STRIDE + s * 8) = v;
        }
    }
    __syncthreads();

    const int w = tid >> 5, lane = tid & 31;
    const int m0 = (w >> 1) * 32;
    const int n0g = (w & 1) * 64;

    float c[2][8][4];
    #pragma unroll
    for (int mt = 0; mt < 2; mt++)
        #pragma unroll
        for (int nt = 0; nt < 8; nt++)
            #pragma unroll
            for (int q = 0; q < 4; q++) c[mt][nt][q] = 0.f;

    const int arow = lane & 15, acol = (lane >> 4) * 8;
    const int brow = lane & 15;

    #pragma unroll
    for (int kc = 0; kc < 8; kc++) {
        const int k0 = kc * 16;
        uint32_t a[2][4];
        #pragma unroll
        for (int mt = 0; mt < 2; mt++) {
            uint32_t addr = smem_u32(As + (m0 + mt * 16 + arow) * AS_STRIDE + k0 + acol);
            ldsm_x4(a[mt][0], a[mt][1], a[mt][2], a[mt][3], addr);
        }
        #pragma unroll
        for (int nt = 0; nt < 8; nt++) {
            uint32_t b[2];
            uint32_t baddr = smem_u32(Ws + (k0 + brow) * AS_STRIDE + n0g + nt * 8);
            ldsm_x2t(b[0], b[1], baddr);
            mma16816(c[0][nt], a[0], b);
            mma16816(c[1][nt], a[1], b);
        }
    }

    #pragma unroll
    for (int mt = 0; mt < 2; mt++) {
        int r0g = row0 + m0 + mt * 16 + (lane >> 2);
        int r1g = r0g + 8;
        float d0 = (r0g < N_NODES) ? g_dinv[r0g] : 0.f;
        float d1 = (r1g < N_NODES) ? g_dinv[r1g] : 0.f;
        #pragma unroll
        for (int nt = 0; nt < 8; nt++) {
            int col = n0g + nt * 8 + 2 * (lane & 3);
            if (r0g < N_NODES) {
                __half2 h = __floats2half2_rn(c[mt][nt][0] * d0, c[mt][nt][1] * d0);
                *reinterpret_cast<__half2*>(g_ph + (size_t)r0g * HIDDEN + col) = h;
            }
            if (r1g < N_NODES) {
                __half2 h = __floats2half2_rn(c[mt][nt][2] * d1, c[mt][nt][3] * d1);
                *reinterpret_cast<__half2*>(g_ph + (size_t)r1g * HIDDEN + col) = h;
            }
        }
    }
}

// ---------------------------------------------------------------------------
// CSR aggregation v1 (proven): one warp per node, lane l owns uint2 (8B),
// one fully-coalesced 256B row load per neighbor. deg = ptr[n+1] - ptr[n].
// ---------------------------------------------------------------------------
__device__ __forceinline__ void acc_h4(float4& acc, uint2 raw) {
    __half2 a = *reinterpret_cast<__half2*>(&raw.x);
    __half2 b = *reinterpret_cast<__half2*>(&raw.y);
    float2 f0 = __half22float2(a);
    float2 f1 = __half22float2(b);
    acc.x += f0.x; acc.y += f0.y; acc.z += f1.x; acc.w += f1.y;
}

template <int LAYER>
__global__ void __launch_bounds__(256) agg_kernel(const float* __restrict__ bias,
                                                  const float* __restrict__ Wl,
                                                  const int* __restrict__ batch) {
    int t = blockIdx.x * blockDim.x + threadIdx.x;
    int n = t >> 5;
    int l = t & 31;
    if (n >= N_NODES) return;

    const uint2* P2 = reinterpret_cast<const uint2*>(g_ph);
    float4 acc = make_float4(0.f, 0.f, 0.f, 0.f);
    acc_h4(acc, __ldg(&P2[(size_t)n * 32 + l]));   // self term

    int base = g_ptr[n];
    int deg  = ((n + 1 < N_NODES) ? g_ptr[n + 1] : N_EDGES) - base;
    int i = 0;
    for (; i + 4 <= deg; i += 4) {
        int s0 = g_csr[base + i + 0];
        int s1 = g_csr[base + i + 1];
        int s2 = g_csr[base + i + 2];
        int s3 = g_csr[base + i + 3];
        uint2 v0 = __ldg(&P2[(size_t)s0 * 32 + l]);
        uint2 v1 = __ldg(&P2[(size_t)s1 * 32 + l]);
        uint2 v2 = __ldg(&P2[(size_t)s2 * 32 + l]);
        uint2 v3 = __ldg(&P2[(size_t)s3 * 32 + l]);
        acc_h4(acc, v0); acc_h4(acc, v1); acc_h4(acc, v2); acc_h4(acc, v3);
    }
    for (; i < deg; i++) {
        int s = g_csr[base + i];
        acc_h4(acc, __ldg(&P2[(size_t)s * 32 + l]));
    }

    float di = g_dinv[n];
    float4 b = __ldg(reinterpret_cast<const float4*>(bias) + l);
    float h0 = fmaxf(di * acc.x + b.x, 0.f);
    float h1 = fmaxf(di * acc.y + b.y, 0.f);
    float h2 = fmaxf(di * acc.z + b.z, 0.f);
    float h3 = fmaxf(di * acc.w + b.w, 0.f);

    if (LAYER == 1) {
        __half2 ha = __floats2half2_rn(h0, h1);
        __half2 hb = __floats2half2_rn(h2, h3);
        uint2 pk;
        pk.x = *reinterpret_cast<uint32_t*>(&ha);
        pk.y = *reinterpret_cast<uint32_t*>(&hb);
        reinterpret_cast<uint2*>(g_hh)[(size_t)n * 32 + l] = pk;
    } else {
        float4 wl = __ldg(reinterpret_cast<const float4*>(Wl) + l);
        float s = h0 * wl.x + h1 * wl.y + h2 * wl.z + h3 * wl.w;
        #pragma unroll
        for (int off = 16; off; off >>= 1) s += __shfl_xor_sync(0xffffffffu, s, off);
        if (l == 0) atomicAdd(&g_pool[__ldg(&batch[n])], s);
    }
}

__global__ void __launch_bounds__(256) out_kernel(float* __restrict__ out,
                                                  const float* __restrict__ bl) {
    int g = blockIdx.x * blockDim.x + threadIdx.x;
    if (g < N_GRAPHS) out[g] = g_pool[g] / fmaxf(g_cnt[g], 1.0f) + bl[0];
}

// ---------------------------------------------------------------------------
extern "C" void kernel_launch(void* const* d_in, const int* in_sizes, int n_in,
                              void* d_out, int out_size) {
    const float* x     = (const float*)d_in[0];
    const int*   ei    = (const int*)  d_in[1];
    const int*   batch = (const int*)  d_in[2];
    const float* W1    = (const float*)d_in[3];
    const float* b1    = (const float*)d_in[4];
    const float* W2    = (const float*)d_in[5];
    const float* b2    = (const float*)d_in[6];
    const float* Wl    = (const float*)d_in[7];
    const float* bl    = (const float*)d_in[8];
    const int* src = ei;
    const int* dst = ei + N_EDGES;

    cudaFuncSetAttribute(gemm_tc<0>, cudaFuncAttributeMaxDynamicSharedMemorySize,
                         GEMM_TC_SMEM);
    cudaFuncSetAttribute(gemm_tc<1>, cudaFuncAttributeMaxDynamicSharedMemorySize,
                         GEMM_TC_SMEM);

    const int EB  = (N_EDGES + 255) / 256;
    const int TCB = (N_NODES + 127) / 128;          // 391
    const int AGB = (N_NODES * 32 + 255) / 256;

    // --- graph structure (4 launches, fill atomic-free via rank trick) ---
    deg_kernel<<<EB, 256>>>(dst);            // + rank capture + pool/cnt restore
    scan_k1<<<SCAN_NB, SCAN_BS>>>(batch);    // + dinv + graph counts
    scan_k3<<<SCAN_NB, SCAN_BS>>>();         // + own offset + g_deg restore
    fill_kernel<<<EB, 256>>>(src, dst);

    // --- layer 1 ---
    gemm_tc<0><<<TCB, 256, GEMM_TC_SMEM>>>(x, W1);
    agg_kernel<1><<<AGB, 256>>>(b1, nullptr, nullptr);

    // --- layer 2 (epilogue + Wl dot + pooling fused) ---
    gemm_tc<1><<<TCB, 256, GEMM_TC_SMEM>>>(nullptr, W2);
    agg_kernel<2><<<AGB, 256>>>(b2, Wl, batch);

    out_kernel<<<(N_GRAPHS + 255) / 256, 256>>>((float*)d_out, bl);
}

// round 14
// speedup vs baseline: 1.0921x; 1.0348x over previous
#include <cuda_runtime.h>
#include <cuda_fp16.h>
#include <cuda_bf16.h>
#include <cstdint>

#define N_NODES  50000
#define N_EDGES  800000
#define HIDDEN   128
#define N_GRAPHS 512

#define SCAN_BS  512
#define SCAN_NB  ((N_NODES + SCAN_BS - 1) / SCAN_BS)   // 98

// ---------------------------------------------------------------------------
// Static device scratch (~33 MB). Referenced ONLY from device code.
// Zero-invariants restored in-call: g_pool/g_cnt zeroed by deg_kernel blk 0
// (before scan_k1 uses them); g_deg zeroed by last reader scan_k3.
// ---------------------------------------------------------------------------
__device__ int    g_deg[N_NODES];
__device__ int    g_ptr[N_NODES];
__device__ int    g_rank[N_EDGES];     // per-edge within-dst rank (from deg pass)
__device__ int    g_csr[N_EDGES];
__device__ int    g_bsum[SCAN_NB];
__device__ float  g_dinv[N_NODES];
__device__ __half g_ph[(size_t)N_NODES * HIDDEN];  // fp16 pre-scaled features
__device__ __half g_hh[(size_t)N_NODES * HIDDEN];  // fp16 relu'd layer-1 output
__device__ float  g_pool[N_GRAPHS];
__device__ float  g_cnt[N_GRAPHS];

// ---------------------------------------------------------------------------
// Degree histogram; atomic return value IS the edge's rank. Block 0 restores
// pool/cnt zeros for this call.
// ---------------------------------------------------------------------------
__global__ void __launch_bounds__(256) deg_kernel(const int* __restrict__ dst) {
    if (blockIdx.x == 0) {
        for (int i = threadIdx.x; i < N_GRAPHS; i += 256) {
            g_pool[i] = 0.0f;
            g_cnt[i]  = 0.0f;
        }
    }
    int e = blockIdx.x * blockDim.x + threadIdx.x;
    if (e < N_EDGES) g_rank[e] = atomicAdd(&g_deg[dst[e]], 1);
}

// scan stage 1 + dinv + graph counts fused
__global__ void __launch_bounds__(SCAN_BS) scan_k1(const int* __restrict__ batch) {
    __shared__ int s[SCAN_BS];
    int i = blockIdx.x * SCAN_BS + threadIdx.x;
    int d = (i < N_NODES) ? g_deg[i] : 0;
    if (i < N_NODES) {
        g_dinv[i] = rsqrtf((float)d + 1.0f);
        atomicAdd(&g_cnt[batch[i]], 1.0f);
    }
    s[threadIdx.x] = d;
    __syncthreads();
    for (int off = SCAN_BS / 2; off > 0; off >>= 1) {
        if (threadIdx.x < off) s[threadIdx.x] += s[threadIdx.x + off];
        __syncthreads();
    }
    if (threadIdx.x == 0) g_bsum[blockIdx.x] = s[0];
}

// Block-local exclusive scan; warp 0 reduces g_bsum[0..b-1] for the block
// offset. Zeroes g_deg (last reader) to restore the cross-call invariant.
__global__ void __launch_bounds__(SCAN_BS) scan_k3() {
    __shared__ int s[SCAN_BS];
    __shared__ int sprefix;
    const int b = blockIdx.x;
    int i = b * SCAN_BS + threadIdx.x;
    int d = (i < N_NODES) ? g_deg[i] : 0;
    if (i < N_NODES) g_deg[i] = 0;                 // self-restore
    s[threadIdx.x] = d;
    __syncthreads();

    if (threadIdx.x < 32) {
        int acc = 0;
        for (int j = threadIdx.x; j < b; j += 32) acc += g_bsum[j];
        #pragma unroll
        for (int off = 16; off; off >>= 1)
            acc += __shfl_xor_sync(0xffffffffu, acc, off);
        if (threadIdx.x == 0) sprefix = acc;
    }

    for (int off = 1; off < SCAN_BS; off <<= 1) {
        int v = (threadIdx.x >= off) ? s[threadIdx.x - off] : 0;
        __syncthreads();
        s[threadIdx.x] += v;
        __syncthreads();
    }
    if (i < N_NODES) g_ptr[i] = sprefix + s[threadIdx.x] - d;   // exclusive
}

// CSR fill with NO atomics: pos = ptr[dst] + rank[e].
__global__ void __launch_bounds__(256) fill_kernel(const int* __restrict__ src,
                                                   const int* __restrict__ dst) {
    int e = blockIdx.x * blockDim.x + threadIdx.x;
    if (e < N_EDGES) {
        int d = dst[e];
        g_csr[g_ptr[d] + g_rank[e]] = src[e];
    }
}

// ---------------------------------------------------------------------------
// Tensor-core GEMM: g_ph[row] = half( (in[row] @ W) * dinv[row] )
//   MODE 0: in = X fp32 (arg)     MODE 1: in = g_hh fp16 (device global)
// ---------------------------------------------------------------------------
#define AS_STRIDE 136
#define GEMM_TC_SMEM (2 * 128 * AS_STRIDE * 2)   // 69632 B

__device__ __forceinline__ uint32_t smem_u32(const void* p) {
    return (uint32_t)__cvta_generic_to_shared(p);
}
__device__ __forceinline__ void ldsm_x4(uint32_t& r0, uint32_t& r1,
                                        uint32_t& r2, uint32_t& r3, uint32_t a) {
    asm volatile("ldmatrix.sync.aligned.m8n8.x4.shared.b16 {%0,%1,%2,%3},[%4];"
                 : "=r"(r0), "=r"(r1), "=r"(r2), "=r"(r3) : "r"(a));
}
__device__ __forceinline__ void ldsm_x2t(uint32_t& r0, uint32_t& r1, uint32_t a) {
    asm volatile("ldmatrix.sync.aligned.m8n8.x2.trans.shared.b16 {%0,%1},[%2];"
                 : "=r"(r0), "=r"(r1) : "r"(a));
}
__device__ __forceinline__ void mma16816(float* c, const uint32_t* a, const uint32_t* b) {
    asm volatile("mma.sync.aligned.m16n8k16.row.col.f32.f16.f16.f32 "
                 "{%0,%1,%2,%3},{%4,%5,%6,%7},{%8,%9},{%0,%1,%2,%3};"
                 : "+f"(c[0]), "+f"(c[1]), "+f"(c[2]), "+f"(c[3])
                 : "r"(a[0]), "r"(a[1]), "r"(a[2]), "r"(a[3]), "r"(b[0]), "r"(b[1]));
}

template <int MODE>
__global__ void __launch_bounds__(256) gemm_tc(const float* __restrict__ X,
                                               const float* __restrict__ W) {
    extern __shared__ __half smem[];
    __half* As = smem;                         // 128 x 136
    __half* Ws = smem + 128 * AS_STRIDE;       // 128 x 136 (row = k, col = n)

    const int tid = threadIdx.x;
    const int row0 = blockIdx.x * 128;

    const float4* W4 = reinterpret_cast<const float4*>(W);
    for (int j = tid; j < 4096; j += 256) {
        int r = j >> 5, s = j & 31;
        float4 v = W4[j];
        __half2 h0 = __floats2half2_rn(v.x, v.y);
        __half2 h1 = __floats2half2_rn(v.z, v.w);
        uint2 pk;
        pk.x = *reinterpret_cast<uint32_t*>(&h0);
        pk.y = *reinterpret_cast<uint32_t*>(&h1);
        *reinterpret_cast<uint2*>(Ws + r * AS_STRIDE + s * 4) = pk;
    }
    if (MODE == 0) {
        for (int j = tid; j < 4096; j += 256) {     // 128 rows x 32 segs
            int r = j >> 5, s = j & 31;
            int row = row0 + r;
            float4 v = make_float4(0.f, 0.f, 0.f, 0.f);
            if (row < N_NODES)
                v = reinterpret_cast<const float4*>(X + (size_t)row * HIDDEN)[s];
            __half2 h0 = __floats2half2_rn(v.x, v.y);
            __half2 h1 = __floats2half2_rn(v.z, v.w);
            uint2 pk;
            pk.x = *reinterpret_cast<uint32_t*>(&h0);
            pk.y = *reinterpret_cast<uint32_t*>(&h1);
            *reinterpret_cast<uint2*>(As + r * AS_STRIDE + s * 4) = pk;
        }
    } else {
        for (int j = tid; j < 2048; j += 256) {     // 128 rows x 16 uint4 segs
            int r = j >> 4, s = j & 15;
            int row = row0 + r;
            uint4 v = make_uint4(0u, 0u, 0u, 0u);
            if (row < N_NODES)
                v = reinterpret_cast<const uint4*>(g_hh)[(size_t)row * 16 + s];
            *reinterpret_cast<uint4*>(As + r * AS_STRIDE + s * 8) = v;
        }
    }
    __syncthreads();

    const int w = tid >> 5, lane = tid & 31;
    const int m0 = (w >> 1) * 32;
    const int n0g = (w & 1) * 64;

    float c[2][8][4];
    #pragma unroll
    for (int mt = 0; mt < 2; mt++)
        #pragma unroll
        for (int nt = 0; nt < 8; nt++)
            #pragma unroll
            for (int q = 0; q < 4; q++) c[mt][nt][q] = 0.f;

    const int arow = lane & 15, acol = (lane >> 4) * 8;
    const int brow = lane & 15;

    #pragma unroll
    for (int kc = 0; kc < 8; kc++) {
        const int k0 = kc * 16;
        uint32_t a[2][4];
        #pragma unroll
        for (int mt = 0; mt < 2; mt++) {
            uint32_t addr = smem_u32(As + (m0 + mt * 16 + arow) * AS_STRIDE + k0 + acol);
            ldsm_x4(a[mt][0], a[mt][1], a[mt][2], a[mt][3], addr);
        }
        #pragma unroll
        for (int nt = 0; nt < 8; nt++) {
            uint32_t b[2];
            uint32_t baddr = smem_u32(Ws + (k0 + brow) * AS_STRIDE + n0g + nt * 8);
            ldsm_x2t(b[0], b[1], baddr);
            mma16816(c[0][nt], a[0], b);
            mma16816(c[1][nt], a[1], b);
        }
    }

    #pragma unroll
    for (int mt = 0; mt < 2; mt++) {
        int r0g = row0 + m0 + mt * 16 + (lane >> 2);
        int r1g = r0g + 8;
        float d0 = (r0g < N_NODES) ? g_dinv[r0g] : 0.f;
        float d1 = (r1g < N_NODES) ? g_dinv[r1g] : 0.f;
        #pragma unroll
        for (int nt = 0; nt < 8; nt++) {
            int col = n0g + nt * 8 + 2 * (lane & 3);
            if (r0g < N_NODES) {
                __half2 h = __floats2half2_rn(c[mt][nt][0] * d0, c[mt][nt][1] * d0);
                *reinterpret_cast<__half2*>(g_ph + (size_t)r0g * HIDDEN + col) = h;
            }
            if (r1g < N_NODES) {
                __half2 h = __floats2half2_rn(c[mt][nt][2] * d1, c[mt][nt][3] * d1);
                *reinterpret_cast<__half2*>(g_ph + (size_t)r1g * HIDDEN + col) = h;
            }
        }
    }
}

// ---------------------------------------------------------------------------
// CSR aggregation v1 (proven): one warp per node, lane l owns uint2 (8B),
// one fully-coalesced 256B row load per neighbor. deg = ptr[n+1] - ptr[n].
// ---------------------------------------------------------------------------
__device__ __forceinline__ void acc_h4(float4& acc, uint2 raw) {
    __half2 a = *reinterpret_cast<__half2*>(&raw.x);
    __half2 b = *reinterpret_cast<__half2*>(&raw.y);
    float2 f0 = __half22float2(a);
    float2 f1 = __half22float2(b);
    acc.x += f0.x; acc.y += f0.y; acc.z += f1.x; acc.w += f1.y;
}

template <int LAYER>
__global__ void __launch_bounds__(256) agg_kernel(const float* __restrict__ bias,
                                                  const float* __restrict__ Wl,
                                                  const int* __restrict__ batch) {
    int t = blockIdx.x * blockDim.x + threadIdx.x;
    int n = t >> 5;
    int l = t & 31;
    if (n >= N_NODES) return;

    const uint2* P2 = reinterpret_cast<const uint2*>(g_ph);
    float4 acc = make_float4(0.f, 0.f, 0.f, 0.f);
    acc_h4(acc, __ldg(&P2[(size_t)n * 32 + l]));   // self term

    int base = g_ptr[n];
    int deg  = ((n + 1 < N_NODES) ? g_ptr[n + 1] : N_EDGES) - base;
    int i = 0;
    for (; i + 4 <= deg; i += 4) {
        int s0 = g_csr[base + i + 0];
        int s1 = g_csr[base + i + 1];
        int s2 = g_csr[base + i + 2];
        int s3 = g_csr[base + i + 3];
        uint2 v0 = __ldg(&P2[(size_t)s0 * 32 + l]);
        uint2 v1 = __ldg(&P2[(size_t)s1 * 32 + l]);
        uint2 v2 = __ldg(&P2[(size_t)s2 * 32 + l]);
        uint2 v3 = __ldg(&P2[(size_t)s3 * 32 + l]);
        acc_h4(acc, v0); acc_h4(acc, v1); acc_h4(acc, v2); acc_h4(acc, v3);
    }
    for (; i < deg; i++) {
        int s = g_csr[base + i];
        acc_h4(acc, __ldg(&P2[(size_t)s * 32 + l]));
    }

    float di = g_dinv[n];
    float4 b = __ldg(reinterpret_cast<const float4*>(bias) + l);
    float h0 = fmaxf(di * acc.x + b.x, 0.f);
    float h1 = fmaxf(di * acc.y + b.y, 0.f);
    float h2 = fmaxf(di * acc.z + b.z, 0.f);
    float h3 = fmaxf(di * acc.w + b.w, 0.f);

    if (LAYER == 1) {
        __half2 ha = __floats2half2_rn(h0, h1);
        __half2 hb = __floats2half2_rn(h2, h3);
        uint2 pk;
        pk.x = *reinterpret_cast<uint32_t*>(&ha);
        pk.y = *reinterpret_cast<uint32_t*>(&hb);
        reinterpret_cast<uint2*>(g_hh)[(size_t)n * 32 + l] = pk;
    } else {
        float4 wl = __ldg(reinterpret_cast<const float4*>(Wl) + l);
        float s = h0 * wl.x + h1 * wl.y + h2 * wl.z + h3 * wl.w;
        #pragma unroll
        for (int off = 16; off; off >>= 1) s += __shfl_xor_sync(0xffffffffu, s, off);
        if (l == 0) atomicAdd(&g_pool[__ldg(&batch[n])], s);
    }
}

__global__ void __launch_bounds__(256) out_kernel(float* __restrict__ out,
                                                  const float* __restrict__ bl) {
    int g = blockIdx.x * blockDim.x + threadIdx.x;
    if (g < N_GRAPHS) out[g] = g_pool[g] / fmaxf(g_cnt[g], 1.0f) + bl[0];
}

// ---------------------------------------------------------------------------
// Launch: fork-join — GEMM1 runs on a second (non-blocking) stream
// concurrently with scan_k3 + fill_kernel. Stream/events are host-side
// objects created once on the first (uncaptured) call.
// ---------------------------------------------------------------------------
extern "C" void kernel_launch(void* const* d_in, const int* in_sizes, int n_in,
                              void* d_out, int out_size) {
    const float* x     = (const float*)d_in[0];
    const int*   ei    = (const int*)  d_in[1];
    const int*   batch = (const int*)  d_in[2];
    const float* W1    = (const float*)d_in[3];
    const float* b1    = (const float*)d_in[4];
    const float* W2    = (const float*)d_in[5];
    const float* b2    = (const float*)d_in[6];
    const float* Wl    = (const float*)d_in[7];
    const float* bl    = (const float*)d_in[8];
    const int* src = ei;
    const int* dst = ei + N_EDGES;

    static cudaStream_t s2 = nullptr;
    static cudaEvent_t evFork = nullptr, evJoin = nullptr;
    if (s2 == nullptr) {
        cudaStreamCreateWithFlags(&s2, cudaStreamNonBlocking);
        cudaEventCreateWithFlags(&evFork, cudaEventDisableTiming);
        cudaEventCreateWithFlags(&evJoin, cudaEventDisableTiming);
    }

    cudaFuncSetAttribute(gemm_tc<0>, cudaFuncAttributeMaxDynamicSharedMemorySize,
                         GEMM_TC_SMEM);
    cudaFuncSetAttribute(gemm_tc<1>, cudaFuncAttributeMaxDynamicSharedMemorySize,
                         GEMM_TC_SMEM);

    const int EB  = (N_EDGES + 255) / 256;
    const int TCB = (N_NODES + 127) / 128;          // 391
    const int AGB = (N_NODES * 32 + 255) / 256;

    // --- prepass head (dinv ready after scan_k1) ---
    deg_kernel<<<EB, 256>>>(dst);            // + rank capture + pool/cnt restore
    scan_k1<<<SCAN_NB, SCAN_BS>>>(batch);    // + dinv + graph counts

    // --- fork: GEMM1 (needs x, W1, dinv only) on s2, parallel to scan_k3+fill
    cudaEventRecord(evFork, 0);
    cudaStreamWaitEvent(s2, evFork, 0);
    gemm_tc<0><<<TCB, 256, GEMM_TC_SMEM, s2>>>(x, W1);
    cudaEventRecord(evJoin, s2);

    scan_k3<<<SCAN_NB, SCAN_BS>>>();         // + own offset + g_deg restore
    fill_kernel<<<EB, 256>>>(src, dst);

    // --- join: agg1 needs both fill (stream order) and GEMM1 (event) ---
    cudaStreamWaitEvent(0, evJoin, 0);
    agg_kernel<1><<<AGB, 256>>>(b1, nullptr, nullptr);

    // --- layer 2 (strict chain) ---
    gemm_tc<1><<<TCB, 256, GEMM_TC_SMEM>>>(nullptr, W2);
    agg_kernel<2><<<AGB, 256>>>(b2, Wl, batch);

    out_kernel<<<(N_GRAPHS + 255) / 256, 256>>>((float*)d_out, bl);
}